// round 6
// baseline (speedup 1.0000x reference)
#include <cuda_runtime.h>
#include <math.h>
#include <stdint.h>

#define Bq   64
#define Tq   512
#define Hq   1024
#define G4   4096
#define MTOT (Bq * Tq)
#define NCTA 128

#define HST     132
#define CHUNK_F (64 * HST)            // 8448 floats per h chunk buffer
#define WB_F    32768                 // resident W: 8192 float4
#define RED_STRIDE 2180               // per-warp partial stride (floats), %32=4
#define HS_REGION 17440               // max(2*CHUNK_F, 8*RED_STRIDE)
#define LSTM_SMEM ((WB_F + HS_REGION) * 4)   // 200832 B

// ---------------- device scratch ----------------
__device__ float g_enc_xproj[(size_t)MTOT * G4];
__device__ float g_dec_xproj[(size_t)MTOT * G4];
__device__ float g_dec_hs  [(size_t)MTOT * Hq];
__device__ float g_h       [2 * Bq * Hq];
__device__ float g_mlp1    [(size_t)MTOT * 256];
__device__ float g_mlp2    [(size_t)MTOT * 128];
__device__ float g_Wt_enc  [(size_t)G4 * Hq];
__device__ float g_Wt_dec  [(size_t)G4 * Hq];
__device__ unsigned g_bars[8];

// ---------------- helpers ----------------
__device__ __forceinline__ float tf32r(float x) {
    uint32_t u; asm("cvt.rna.tf32.f32 %0, %1;" : "=r"(u) : "f"(x));
    return __uint_as_float(u);
}
__device__ __forceinline__ uint32_t fu(float x) { return __float_as_uint(x); }
__device__ __forceinline__ void mma_tf32(float c[4],
    uint32_t a0, uint32_t a1, uint32_t a2, uint32_t a3, uint32_t b0, uint32_t b1) {
    asm volatile(
        "mma.sync.aligned.m16n8k8.row.col.f32.tf32.tf32.f32 "
        "{%0,%1,%2,%3}, {%4,%5,%6,%7}, {%8,%9}, {%0,%1,%2,%3};"
        : "+f"(c[0]), "+f"(c[1]), "+f"(c[2]), "+f"(c[3])
        : "r"(a0), "r"(a1), "r"(a2), "r"(a3), "r"(b0), "r"(b1));
}
__device__ __forceinline__ float sigm(float x) { return 1.f / (1.f + expf(-x)); }

// ---------------- init ----------------
__global__ void zero_hc_kernel() {
    int i = blockIdx.x * blockDim.x + threadIdx.x;
    if (i < Bq * Hq) g_h[i] = 0.f;
    if (i < 8) g_bars[i] = 0u;
}

// ---------------- Whh prep (fragment-packed, layout verified in R5) ---------
__global__ __launch_bounds__(256)
void prep_w_kernel(const float* __restrict__ Whh, float4* __restrict__ Wt4) {
    int idx  = blockIdx.x * 256 + threadIdx.x;
    int lane = idx & 31;
    int p    = (idx >> 5) & 1;
    int gks  = (idx >> 6) & 127;
    int cta  = idx >> 13;
    int g = lane >> 2, tq = lane & 3;
    int k0 = gks * 8 + tq, k1 = k0 + 4;
    int c0 = p * 16 + g,  c1 = c0 + 8;
    size_t r0 = (size_t)((c0 >> 3) * Hq + cta * 8 + (c0 & 7)) * Hq;
    size_t r1 = (size_t)((c1 >> 3) * Hq + cta * 8 + (c1 & 7)) * Hq;
    float4 v;
    v.x = tf32r(Whh[r0 + k0]); v.y = tf32r(Whh[r0 + k1]);
    v.z = tf32r(Whh[r1 + k0]); v.w = tf32r(Whh[r1 + k1]);
    Wt4[idx] = v;
}

// ---------------- tf32 GEMM (unchanged from R5) ------------------------------
__global__ __launch_bounds__(256)
void gemm_tf32_kernel(const float* __restrict__ A, const float* __restrict__ W,
                      const float* __restrict__ bias1, const float* __restrict__ bias2,
                      float* __restrict__ C, int M, int N, int K, int relu)
{
    __shared__ float As[32][132];
    __shared__ float Bs[32][132];
    const int tid = threadIdx.x;
    const int lane = tid & 31, wid = tid >> 5;
    const int g = lane >> 2, tq = lane & 3;
    const int wm = wid >> 1, wn = wid & 1;
    const int bm = blockIdx.y * 128, bn = blockIdx.x * 128;
    const int kq = tid & 7, lr = tid >> 3;

    float acc[2][8][4] = {};
    float4 pa[4], pb[4];

#pragma unroll
    for (int p = 0; p < 4; p++) {
        pa[p] = *(const float4*)&A[(size_t)(bm + lr + p * 32) * K + kq * 4];
        pb[p] = *(const float4*)&W[(size_t)(bn + lr + p * 32) * K + kq * 4];
    }
#pragma unroll
    for (int p = 0; p < 4; p++) {
        int m = lr + p * 32;
        As[kq*4+0][m] = tf32r(pa[p].x); As[kq*4+1][m] = tf32r(pa[p].y);
        As[kq*4+2][m] = tf32r(pa[p].z); As[kq*4+3][m] = tf32r(pa[p].w);
        Bs[kq*4+0][m] = tf32r(pb[p].x); Bs[kq*4+1][m] = tf32r(pb[p].y);
        Bs[kq*4+2][m] = tf32r(pb[p].z); Bs[kq*4+3][m] = tf32r(pb[p].w);
    }
    __syncthreads();

    const int NK = K / 32;
    for (int kt = 0; kt < NK; kt++) {
        if (kt + 1 < NK) {
            int k0 = (kt + 1) * 32;
#pragma unroll
            for (int p = 0; p < 4; p++) {
                pa[p] = *(const float4*)&A[(size_t)(bm + lr + p * 32) * K + k0 + kq * 4];
                pb[p] = *(const float4*)&W[(size_t)(bn + lr + p * 32) * K + k0 + kq * 4];
            }
        }
#pragma unroll
        for (int ks = 0; ks < 4; ks++) {
            const int kb = ks * 8;
            uint32_t a[2][4], b[8][2];
#pragma unroll
            for (int mf = 0; mf < 2; mf++) {
                int r = wm * 32 + mf * 16 + g;
                a[mf][0] = fu(As[kb + tq][r]);     a[mf][1] = fu(As[kb + tq][r + 8]);
                a[mf][2] = fu(As[kb + tq + 4][r]); a[mf][3] = fu(As[kb + tq + 4][r + 8]);
            }
#pragma unroll
            for (int nf = 0; nf < 8; nf++) {
                int cn = wn * 64 + nf * 8 + g;
                b[nf][0] = fu(Bs[kb + tq][cn]);
                b[nf][1] = fu(Bs[kb + tq + 4][cn]);
            }
#pragma unroll
            for (int mf = 0; mf < 2; mf++)
#pragma unroll
                for (int nf = 0; nf < 8; nf++)
                    mma_tf32(acc[mf][nf], a[mf][0], a[mf][1], a[mf][2], a[mf][3],
                             b[nf][0], b[nf][1]);
        }
        __syncthreads();
        if (kt + 1 < NK) {
#pragma unroll
            for (int p = 0; p < 4; p++) {
                int m = lr + p * 32;
                As[kq*4+0][m] = tf32r(pa[p].x); As[kq*4+1][m] = tf32r(pa[p].y);
                As[kq*4+2][m] = tf32r(pa[p].z); As[kq*4+3][m] = tf32r(pa[p].w);
                Bs[kq*4+0][m] = tf32r(pb[p].x); Bs[kq*4+1][m] = tf32r(pb[p].y);
                Bs[kq*4+2][m] = tf32r(pb[p].z); Bs[kq*4+3][m] = tf32r(pb[p].w);
            }
            __syncthreads();
        }
    }

#pragma unroll
    for (int mf = 0; mf < 2; mf++) {
        int row = bm + wm * 32 + mf * 16 + g;
#pragma unroll
        for (int nf = 0; nf < 8; nf++) {
            int col = bn + wn * 64 + nf * 8 + 2 * tq;
            float b0 = 0.f, b1 = 0.f;
            if (bias1) { b0 = bias1[col]; b1 = bias1[col + 1]; }
            if (bias2) { b0 += bias2[col]; b1 += bias2[col + 1]; }
            float v0 = acc[mf][nf][0] + b0, v1 = acc[mf][nf][1] + b1;
            float v2 = acc[mf][nf][2] + b0, v3 = acc[mf][nf][3] + b1;
            if (relu) { v0 = fmaxf(v0, 0.f); v1 = fmaxf(v1, 0.f);
                        v2 = fmaxf(v2, 0.f); v3 = fmaxf(v3, 0.f); }
            float2 lo = {v0, v1}, hi = {v2, v3};
            *(float2*)&C[(size_t)row * N + col] = lo;
            *(float2*)&C[(size_t)(row + 8) * N + col] = hi;
        }
    }
}

// ---------------- striped grid barrier ---------------------------------------
__device__ __forceinline__ void grid_bar(unsigned total_target) {
    __syncthreads();
    if (threadIdx.x == 0) {
        __threadfence();
        atomicAdd(&g_bars[blockIdx.x & 7], 1u);   // result unused -> RED
        volatile unsigned* p = g_bars;
        for (;;) {
            unsigned sum = 0;
#pragma unroll
            for (int i = 0; i < 8; i++) sum += p[i];
            if (sum >= total_target) break;
        }
        __threadfence();
    }
    __syncthreads();
}

// ---------------- persistent LSTM recurrence (k-strided warp split) ----------
__global__ __launch_bounds__(256, 1)
void lstm_persistent_kernel(const float* __restrict__ enc_xp,
                            const float* __restrict__ dec_xp,
                            float* __restrict__ dec_hs)
{
    extern __shared__ float smem[];
    float4* Wb4 = (float4*)smem;            // resident W (128 KB)
    float*  HsA = smem + WB_F;              // 2 h chunk buffers / Red (aliased)
    float*  Red = HsA;

    const int tid  = threadIdx.x;
    const int lane = tid & 31, wid = tid >> 5;
    const int g = lane >> 2, tq = lane & 3;
    const int j0 = blockIdx.x * 8;
    const int ldrow = tid >> 5;
    const int ldc4  = (tid & 31) * 4;
    const int pm = tid >> 2;                // pointwise row 0..63
    const int pj = (tid & 3) * 2;           // pointwise col pair
    const int pcol = j0 + pj;

    const float4* WtE = (const float4*)g_Wt_enc + (size_t)blockIdx.x * 8192;
    const float4* WtD = (const float4*)g_Wt_dec + (size_t)blockIdx.x * 8192;

    float2 creg = {0.f, 0.f};

    for (int s = 0; s < 2 * Tq; s++) {
        const int enc = (s < Tq);
        const int t   = enc ? s : (s - Tq);
        const float* __restrict__ xproj = enc ? enc_xp : dec_xp;
        const float* __restrict__ h_in  = g_h + (s & 1) * (Bq * Hq);
        float* __restrict__ h_out       = g_h + ((s + 1) & 1) * (Bq * Hq);

        if (s == 0 || s == Tq) {
            const float4* src = enc ? WtE : WtD;
#pragma unroll
            for (int j = 0; j < 32; j++) Wb4[j * 256 + tid] = src[j * 256 + tid];
            __syncthreads();
        }

        // prefetch xproj gates (DRAM latency overlap)
        float2 xg[4];
        {
            size_t xb = ((size_t)pm * Tq + t) * G4 + pcol;
#pragma unroll
            for (int gg = 0; gg < 4; gg++)
                xg[gg] = *(const float2*)&xproj[xb + (size_t)gg * Hq];
        }

        // warp computes full 64x32 tile over k8-steps {wid, wid+8} of each chunk
        float acc[4][4][4] = {};

        float4 pre[8];
#pragma unroll
        for (int p = 0; p < 8; p++)
            pre[p] = __ldcg((const float4*)&h_in[(p * 8 + ldrow) * Hq + ldc4]);
#pragma unroll
        for (int p = 0; p < 8; p++) {
            float4 r; r.x = tf32r(pre[p].x); r.y = tf32r(pre[p].y);
                      r.z = tf32r(pre[p].z); r.w = tf32r(pre[p].w);
            *(float4*)&HsA[(p * 8 + ldrow) * HST + ldc4] = r;
        }
        __syncthreads();

        for (int kt = 0; kt < 8; kt++) {
            if (kt < 7) {
                const int k0 = (kt + 1) * 128;
#pragma unroll
                for (int p = 0; p < 8; p++)
                    pre[p] = __ldcg((const float4*)&h_in[(p * 8 + ldrow) * Hq + k0 + ldc4]);
            }
            const float* Hs = HsA + (kt & 1) * CHUNK_F;
#pragma unroll
            for (int which = 0; which < 2; which++) {
                const int kl  = wid + which * 8;        // local k8-step 0..15
                const int kb  = kl * 8;
                const int gks = kt * 16 + kl;
                float4 f0 = Wb4[(gks * 2 + 0) * 32 + lane];
                float4 f1 = Wb4[(gks * 2 + 1) * 32 + lane];
                uint32_t b[4][2] = { {fu(f0.x), fu(f0.y)}, {fu(f0.z), fu(f0.w)},
                                     {fu(f1.x), fu(f1.y)}, {fu(f1.z), fu(f1.w)} };
#pragma unroll
                for (int mf = 0; mf < 4; mf++) {
                    const int r = mf * 16 + g;
                    uint32_t a0 = fu(Hs[r * HST + kb + tq]);
                    uint32_t a1 = fu(Hs[(r + 8) * HST + kb + tq]);
                    uint32_t a2 = fu(Hs[r * HST + kb + tq + 4]);
                    uint32_t a3 = fu(Hs[(r + 8) * HST + kb + tq + 4]);
#pragma unroll
                    for (int nt = 0; nt < 4; nt++)
                        mma_tf32(acc[mf][nt], a0, a1, a2, a3, b[nt][0], b[nt][1]);
                }
            }
            if (kt < 7) {
                float* HsN = HsA + ((kt + 1) & 1) * CHUNK_F;
#pragma unroll
                for (int p = 0; p < 8; p++) {
                    float4 r; r.x = tf32r(pre[p].x); r.y = tf32r(pre[p].y);
                              r.z = tf32r(pre[p].z); r.w = tf32r(pre[p].w);
                    *(float4*)&HsN[(p * 8 + ldrow) * HST + ldc4] = r;
                }
            }
            __syncthreads();
        }

        // write per-warp partials: Red[w][row*34 + col] (rows 0..63, cols 0..31)
        {
            float* Rw = Red + wid * RED_STRIDE;
#pragma unroll
            for (int mf = 0; mf < 4; mf++)
#pragma unroll
                for (int nt = 0; nt < 4; nt++) {
                    int col = nt * 8 + 2 * tq;
                    float2 lo = {acc[mf][nt][0], acc[mf][nt][1]};
                    float2 hi = {acc[mf][nt][2], acc[mf][nt][3]};
                    *(float2*)&Rw[(mf * 16 + g) * 34 + col]     = lo;
                    *(float2*)&Rw[(mf * 16 + 8 + g) * 34 + col] = hi;
                }
        }
        __syncthreads();

        // fused reduce + pointwise: thread sums its 8 gate values over 8 partials
        {
            float2 gv[4] = {{0,0},{0,0},{0,0},{0,0}};
#pragma unroll
            for (int p = 0; p < 8; p++) {
                const float* rp = Red + p * RED_STRIDE + pm * 34 + pj;
#pragma unroll
                for (int gg = 0; gg < 4; gg++) {
                    float2 v = *(const float2*)&rp[gg * 8];
                    gv[gg].x += v.x; gv[gg].y += v.y;
                }
            }
            float hn0, hn1;
            {
                float ig = gv[0].x + xg[0].x, fg = gv[1].x + xg[1].x;
                float gg = gv[2].x + xg[2].x, og = gv[3].x + xg[3].x;
                float cn = sigm(fg) * creg.x + sigm(ig) * tanhf(gg);
                creg.x = cn; hn0 = sigm(og) * tanhf(cn);
            }
            {
                float ig = gv[0].y + xg[0].y, fg = gv[1].y + xg[1].y;
                float gg = gv[2].y + xg[2].y, og = gv[3].y + xg[3].y;
                float cn = sigm(fg) * creg.y + sigm(ig) * tanhf(gg);
                creg.y = cn; hn1 = sigm(og) * tanhf(cn);
            }
            float2 hv = {hn0, hn1};
            *(float2*)&h_out[pm * Hq + pcol] = hv;
            if (!enc) *(float2*)&dec_hs[((size_t)pm * Tq + t) * Hq + pcol] = hv;
        }

        grid_bar((unsigned)(s + 1) * NCTA);
    }
}

// ---------------- host driver ------------------------------------------------
extern "C" void kernel_launch(void* const* d_in, const int* in_sizes, int n_in,
                              void* d_out, int out_size)
{
    const float* input_seq  = (const float*)d_in[0];
    const float* target_seq = (const float*)d_in[1];
    const float* enc_Wih = (const float*)d_in[2];
    const float* enc_Whh = (const float*)d_in[3];
    const float* enc_bih = (const float*)d_in[4];
    const float* enc_bhh = (const float*)d_in[5];
    const float* dec_Wih = (const float*)d_in[6];
    const float* dec_Whh = (const float*)d_in[7];
    const float* dec_bih = (const float*)d_in[8];
    const float* dec_bhh = (const float*)d_in[9];
    const float* W1 = (const float*)d_in[10];
    const float* b1 = (const float*)d_in[11];
    const float* W2 = (const float*)d_in[12];
    const float* b2 = (const float*)d_in[13];
    const float* W3 = (const float*)d_in[14];
    const float* b3 = (const float*)d_in[15];
    float* out = (float*)d_out;

    float *enc_xp, *dec_xp, *dec_hs, *m1, *m2, *wte, *wtd;
    cudaGetSymbolAddress((void**)&enc_xp, g_enc_xproj);
    cudaGetSymbolAddress((void**)&dec_xp, g_dec_xproj);
    cudaGetSymbolAddress((void**)&dec_hs, g_dec_hs);
    cudaGetSymbolAddress((void**)&m1,     g_mlp1);
    cudaGetSymbolAddress((void**)&m2,     g_mlp2);
    cudaGetSymbolAddress((void**)&wte,    g_Wt_enc);
    cudaGetSymbolAddress((void**)&wtd,    g_Wt_dec);

    static int smem_set = 0;
    if (!smem_set) {
        cudaFuncSetAttribute(lstm_persistent_kernel,
                             cudaFuncAttributeMaxDynamicSharedMemorySize, LSTM_SMEM);
        smem_set = 1;
    }

    zero_hc_kernel<<<(Bq * Hq + 255) / 256, 256>>>();

    prep_w_kernel<<<4096, 256>>>(enc_Whh, (float4*)wte);
    prep_w_kernel<<<4096, 256>>>(dec_Whh, (float4*)wtd);

    gemm_tf32_kernel<<<dim3(G4 / 128, MTOT / 128), 256>>>(
        input_seq, enc_Wih, enc_bih, enc_bhh, enc_xp, MTOT, G4, 256, 0);
    gemm_tf32_kernel<<<dim3(G4 / 128, MTOT / 128), 256>>>(
        target_seq, dec_Wih, dec_bih, dec_bhh, dec_xp, MTOT, G4, Hq, 0);

    lstm_persistent_kernel<<<NCTA, 256, LSTM_SMEM>>>(enc_xp, dec_xp, dec_hs);

    gemm_tf32_kernel<<<dim3(256 / 128, MTOT / 128), 256>>>(
        dec_hs, W1, b1, nullptr, m1, MTOT, 256, Hq, 1);
    gemm_tf32_kernel<<<dim3(128 / 128, MTOT / 128), 256>>>(
        m1, W2, b2, nullptr, m2, MTOT, 128, 256, 1);
    gemm_tf32_kernel<<<dim3(256 / 128, MTOT / 128), 256>>>(
        m2, W3, b3, nullptr, out, MTOT, 256, 128, 0);
}

// round 7
// speedup vs baseline: 1.0571x; 1.0571x over previous
#include <cuda_runtime.h>
#include <math.h>
#include <stdint.h>

#define Bq   64
#define Tq   512
#define Hq   1024
#define G4   4096
#define MTOT (Bq * Tq)
#define NCTA 128

#define HST     132
#define CHUNK_F (64 * HST)          // 8448 floats per h chunk buffer
#define WB_F    32768               // resident W: 8192 float4
#define LSTM_SMEM ((WB_F + 2 * CHUNK_F) * 4)   // 198656 B

#define BARPAD 32                   // 128B per counter -> distinct L2 lines

// ---------------- device scratch ----------------
__device__ float g_enc_xproj[(size_t)MTOT * G4];
__device__ float g_dec_xproj[(size_t)MTOT * G4];
__device__ float g_dec_hs  [(size_t)MTOT * Hq];
__device__ float g_h       [2 * Bq * Hq];
__device__ float g_mlp1    [(size_t)MTOT * 256];
__device__ float g_mlp2    [(size_t)MTOT * 128];
__device__ float g_Wt_enc  [(size_t)G4 * Hq];   // fragment-packed per CTA
__device__ float g_Wt_dec  [(size_t)G4 * Hq];
__device__ unsigned g_bars[32 * BARPAD];

// ---------------- helpers ----------------
__device__ __forceinline__ float tf32r(float x) {
    uint32_t u; asm("cvt.rna.tf32.f32 %0, %1;" : "=r"(u) : "f"(x));
    return __uint_as_float(u);
}
__device__ __forceinline__ uint32_t fu(float x) { return __float_as_uint(x); }
__device__ __forceinline__ void mma_tf32(float c[4],
    uint32_t a0, uint32_t a1, uint32_t a2, uint32_t a3, uint32_t b0, uint32_t b1) {
    asm volatile(
        "mma.sync.aligned.m16n8k8.row.col.f32.tf32.tf32.f32 "
        "{%0,%1,%2,%3}, {%4,%5,%6,%7}, {%8,%9}, {%0,%1,%2,%3};"
        : "+f"(c[0]), "+f"(c[1]), "+f"(c[2]), "+f"(c[3])
        : "r"(a0), "r"(a1), "r"(a2), "r"(a3), "r"(b0), "r"(b1));
}
__device__ __forceinline__ float sigm(float x) { return 1.f / (1.f + expf(-x)); }

// ---------------- init ----------------
__global__ void zero_hc_kernel() {
    int i = blockIdx.x * blockDim.x + threadIdx.x;
    if (i < Bq * Hq) g_h[i] = 0.f;
    if (i < 32 * BARPAD) g_bars[i] = 0u;
}

// ---------------- Whh prep (fragment-packed, layout verified in R5) ---------
__global__ __launch_bounds__(256)
void prep_w_kernel(const float* __restrict__ Whh, float4* __restrict__ Wt4) {
    int idx  = blockIdx.x * 256 + threadIdx.x;
    int lane = idx & 31;
    int p    = (idx >> 5) & 1;
    int gks  = (idx >> 6) & 127;
    int cta  = idx >> 13;
    int g = lane >> 2, tq = lane & 3;
    int k0 = gks * 8 + tq, k1 = k0 + 4;
    int c0 = p * 16 + g,  c1 = c0 + 8;
    size_t r0 = (size_t)((c0 >> 3) * Hq + cta * 8 + (c0 & 7)) * Hq;
    size_t r1 = (size_t)((c1 >> 3) * Hq + cta * 8 + (c1 & 7)) * Hq;
    float4 v;
    v.x = tf32r(Whh[r0 + k0]); v.y = tf32r(Whh[r0 + k1]);
    v.z = tf32r(Whh[r1 + k0]); v.w = tf32r(Whh[r1 + k1]);
    Wt4[idx] = v;
}

// ---------------- tf32 GEMM (unchanged) --------------------------------------
__global__ __launch_bounds__(256)
void gemm_tf32_kernel(const float* __restrict__ A, const float* __restrict__ W,
                      const float* __restrict__ bias1, const float* __restrict__ bias2,
                      float* __restrict__ C, int M, int N, int K, int relu)
{
    __shared__ float As[32][132];
    __shared__ float Bs[32][132];
    const int tid = threadIdx.x;
    const int lane = tid & 31, wid = tid >> 5;
    const int g = lane >> 2, tq = lane & 3;
    const int wm = wid >> 1, wn = wid & 1;
    const int bm = blockIdx.y * 128, bn = blockIdx.x * 128;
    const int kq = tid & 7, lr = tid >> 3;

    float acc[2][8][4] = {};
    float4 pa[4], pb[4];

#pragma unroll
    for (int p = 0; p < 4; p++) {
        pa[p] = *(const float4*)&A[(size_t)(bm + lr + p * 32) * K + kq * 4];
        pb[p] = *(const float4*)&W[(size_t)(bn + lr + p * 32) * K + kq * 4];
    }
#pragma unroll
    for (int p = 0; p < 4; p++) {
        int m = lr + p * 32;
        As[kq*4+0][m] = tf32r(pa[p].x); As[kq*4+1][m] = tf32r(pa[p].y);
        As[kq*4+2][m] = tf32r(pa[p].z); As[kq*4+3][m] = tf32r(pa[p].w);
        Bs[kq*4+0][m] = tf32r(pb[p].x); Bs[kq*4+1][m] = tf32r(pb[p].y);
        Bs[kq*4+2][m] = tf32r(pb[p].z); Bs[kq*4+3][m] = tf32r(pb[p].w);
    }
    __syncthreads();

    const int NK = K / 32;
    for (int kt = 0; kt < NK; kt++) {
        if (kt + 1 < NK) {
            int k0 = (kt + 1) * 32;
#pragma unroll
            for (int p = 0; p < 4; p++) {
                pa[p] = *(const float4*)&A[(size_t)(bm + lr + p * 32) * K + k0 + kq * 4];
                pb[p] = *(const float4*)&W[(size_t)(bn + lr + p * 32) * K + k0 + kq * 4];
            }
        }
#pragma unroll
        for (int ks = 0; ks < 4; ks++) {
            const int kb = ks * 8;
            uint32_t a[2][4], b[8][2];
#pragma unroll
            for (int mf = 0; mf < 2; mf++) {
                int r = wm * 32 + mf * 16 + g;
                a[mf][0] = fu(As[kb + tq][r]);     a[mf][1] = fu(As[kb + tq][r + 8]);
                a[mf][2] = fu(As[kb + tq + 4][r]); a[mf][3] = fu(As[kb + tq + 4][r + 8]);
            }
#pragma unroll
            for (int nf = 0; nf < 8; nf++) {
                int cn = wn * 64 + nf * 8 + g;
                b[nf][0] = fu(Bs[kb + tq][cn]);
                b[nf][1] = fu(Bs[kb + tq + 4][cn]);
            }
#pragma unroll
            for (int mf = 0; mf < 2; mf++)
#pragma unroll
                for (int nf = 0; nf < 8; nf++)
                    mma_tf32(acc[mf][nf], a[mf][0], a[mf][1], a[mf][2], a[mf][3],
                             b[nf][0], b[nf][1]);
        }
        __syncthreads();
        if (kt + 1 < NK) {
#pragma unroll
            for (int p = 0; p < 4; p++) {
                int m = lr + p * 32;
                As[kq*4+0][m] = tf32r(pa[p].x); As[kq*4+1][m] = tf32r(pa[p].y);
                As[kq*4+2][m] = tf32r(pa[p].z); As[kq*4+3][m] = tf32r(pa[p].w);
                Bs[kq*4+0][m] = tf32r(pb[p].x); Bs[kq*4+1][m] = tf32r(pb[p].y);
                Bs[kq*4+2][m] = tf32r(pb[p].z); Bs[kq*4+3][m] = tf32r(pb[p].w);
            }
            __syncthreads();
        }
    }

#pragma unroll
    for (int mf = 0; mf < 2; mf++) {
        int row = bm + wm * 32 + mf * 16 + g;
#pragma unroll
        for (int nf = 0; nf < 8; nf++) {
            int col = bn + wn * 64 + nf * 8 + 2 * tq;
            float b0 = 0.f, b1 = 0.f;
            if (bias1) { b0 = bias1[col]; b1 = bias1[col + 1]; }
            if (bias2) { b0 += bias2[col]; b1 += bias2[col + 1]; }
            float v0 = acc[mf][nf][0] + b0, v1 = acc[mf][nf][1] + b1;
            float v2 = acc[mf][nf][2] + b0, v3 = acc[mf][nf][3] + b1;
            if (relu) { v0 = fmaxf(v0, 0.f); v1 = fmaxf(v1, 0.f);
                        v2 = fmaxf(v2, 0.f); v3 = fmaxf(v3, 0.f); }
            float2 lo = {v0, v1}, hi = {v2, v3};
            *(float2*)&C[(size_t)row * N + col] = lo;
            *(float2*)&C[(size_t)(row + 8) * N + col] = hi;
        }
    }
}

// ---------------- fast grid barrier ------------------------------------------
// 32 counters on distinct 128B lines, 4 CTAs arrive per counter (bid&31).
// Wait: lanes 0..31 of warp 0 poll one counter each in parallel.
__device__ __forceinline__ void grid_bar(unsigned step) {
    __syncthreads();
    if (threadIdx.x == 0) {
        __threadfence();
        atomicAdd(&g_bars[(blockIdx.x & 31) * BARPAD], 1u);
    }
    if (threadIdx.x < 32) {
        volatile unsigned* p = &g_bars[threadIdx.x * BARPAD];
        const unsigned target = step * (NCTA / 32);
        while (*p < target) { }
        __threadfence();
    }
    __syncthreads();
}

// ---------------- persistent LSTM recurrence (R5 structure) ------------------
__global__ __launch_bounds__(256, 1)
void lstm_persistent_kernel(const float* __restrict__ enc_xp,
                            const float* __restrict__ dec_xp,
                            float* __restrict__ dec_hs)
{
    extern __shared__ float smem[];
    float4* Wb4 = (float4*)smem;            // resident W (128 KB)
    float*  HsA = smem + WB_F;              // 2 h chunk buffers

    const int tid  = threadIdx.x;
    const int lane = tid & 31, wid = tid >> 5;
    const int g = lane >> 2, tq = lane & 3;
    const int wm = wid >> 1, wn = wid & 1;  // 4m x 2n warps
    const int r0 = wm * 16 + g;
    const int j0 = blockIdx.x * 8;
    const int ldrow = tid >> 5;
    const int ldc4  = (tid & 31) * 4;
    const int pm = tid >> 2;                // pointwise row 0..63
    const int pj = (tid & 3) * 2;           // pointwise col pair
    const int pcol = j0 + pj;

    const float4* WtE = (const float4*)g_Wt_enc + (size_t)blockIdx.x * 8192;
    const float4* WtD = (const float4*)g_Wt_dec + (size_t)blockIdx.x * 8192;

    float2 creg = {0.f, 0.f};

    for (int s = 0; s < 2 * Tq; s++) {
        const int enc = (s < Tq);
        const int t   = enc ? s : (s - Tq);
        const float* __restrict__ xproj = enc ? enc_xp : dec_xp;
        const float* __restrict__ h_in  = g_h + (s & 1) * (Bq * Hq);
        float* __restrict__ h_out       = g_h + ((s + 1) & 1) * (Bq * Hq);

        if (s == 0 || s == Tq) {
            const float4* src = enc ? WtE : WtD;
#pragma unroll
            for (int j = 0; j < 32; j++) Wb4[j * 256 + tid] = src[j * 256 + tid];
            __syncthreads();
        }

        // prefetch xproj gates (DRAM latency overlap)
        float2 xg[4];
        {
            size_t xb = ((size_t)pm * Tq + t) * G4 + pcol;
#pragma unroll
            for (int gg = 0; gg < 4; gg++)
                xg[gg] = *(const float2*)&xproj[xb + (size_t)gg * Hq];
        }

        float acc[2][4] = {};

        float4 pre[8];
#pragma unroll
        for (int p = 0; p < 8; p++)
            pre[p] = __ldcg((const float4*)&h_in[(p * 8 + ldrow) * Hq + ldc4]);
#pragma unroll
        for (int p = 0; p < 8; p++) {
            float4 r; r.x = tf32r(pre[p].x); r.y = tf32r(pre[p].y);
                      r.z = tf32r(pre[p].z); r.w = tf32r(pre[p].w);
            *(float4*)&HsA[(p * 8 + ldrow) * HST + ldc4] = r;
        }
        __syncthreads();

        for (int kt = 0; kt < 8; kt++) {
            if (kt < 7) {
                const int k0 = (kt + 1) * 128;
#pragma unroll
                for (int p = 0; p < 8; p++)
                    pre[p] = __ldcg((const float4*)&h_in[(p * 8 + ldrow) * Hq + k0 + ldc4]);
            }
            const float* Hs = HsA + (kt & 1) * CHUNK_F;
#pragma unroll
            for (int ks = 0; ks < 16; ks++) {
                const int kb = ks * 8;
                float4 wv = Wb4[(((kt * 16 + ks) * 2) + wn) * 32 + lane];
                uint32_t a0 = fu(Hs[r0 * HST + kb + tq]);
                uint32_t a1 = fu(Hs[(r0 + 8) * HST + kb + tq]);
                uint32_t a2 = fu(Hs[r0 * HST + kb + tq + 4]);
                uint32_t a3 = fu(Hs[(r0 + 8) * HST + kb + tq + 4]);
                mma_tf32(acc[0], a0, a1, a2, a3, fu(wv.x), fu(wv.y));
                mma_tf32(acc[1], a0, a1, a2, a3, fu(wv.z), fu(wv.w));
            }
            if (kt < 7) {
                float* HsN = HsA + ((kt + 1) & 1) * CHUNK_F;
#pragma unroll
                for (int p = 0; p < 8; p++) {
                    float4 r; r.x = tf32r(pre[p].x); r.y = tf32r(pre[p].y);
                              r.z = tf32r(pre[p].z); r.w = tf32r(pre[p].w);
                    *(float4*)&HsN[(p * 8 + ldrow) * HST + ldc4] = r;
                }
            }
            __syncthreads();
        }

        // stage gate tile: Cs[m][0..31] stride 33 (aliases h buffer 0)
        float* Cs = HsA;
        {
            int cb = wn * 16;
#pragma unroll
            for (int nt = 0; nt < 2; nt++) {
                int col = cb + nt * 8 + 2 * tq;
                Cs[r0 * 33 + col]           = acc[nt][0];
                Cs[r0 * 33 + col + 1]       = acc[nt][1];
                Cs[(r0 + 8) * 33 + col]     = acc[nt][2];
                Cs[(r0 + 8) * 33 + col + 1] = acc[nt][3];
            }
        }
        __syncthreads();

        // pointwise: 2 columns per thread, c in registers
        {
            const float* cr = &Cs[pm * 33 + pj];
            float hn0, hn1;
            {
                float ig = cr[0]  + xg[0].x;
                float fg = cr[8]  + xg[1].x;
                float gg = cr[16] + xg[2].x;
                float og = cr[24] + xg[3].x;
                float cn = sigm(fg) * creg.x + sigm(ig) * tanhf(gg);
                creg.x = cn; hn0 = sigm(og) * tanhf(cn);
            }
            {
                float ig = cr[1]  + xg[0].y;
                float fg = cr[9]  + xg[1].y;
                float gg = cr[17] + xg[2].y;
                float og = cr[25] + xg[3].y;
                float cn = sigm(fg) * creg.y + sigm(ig) * tanhf(gg);
                creg.y = cn; hn1 = sigm(og) * tanhf(cn);
            }
            float2 hv = {hn0, hn1};
            *(float2*)&h_out[pm * Hq + pcol] = hv;
            if (!enc) *(float2*)&dec_hs[((size_t)pm * Tq + t) * Hq + pcol] = hv;
        }

        grid_bar((unsigned)(s + 1));
    }
}

// ---------------- host driver ------------------------------------------------
extern "C" void kernel_launch(void* const* d_in, const int* in_sizes, int n_in,
                              void* d_out, int out_size)
{
    const float* input_seq  = (const float*)d_in[0];
    const float* target_seq = (const float*)d_in[1];
    const float* enc_Wih = (const float*)d_in[2];
    const float* enc_Whh = (const float*)d_in[3];
    const float* enc_bih = (const float*)d_in[4];
    const float* enc_bhh = (const float*)d_in[5];
    const float* dec_Wih = (const float*)d_in[6];
    const float* dec_Whh = (const float*)d_in[7];
    const float* dec_bih = (const float*)d_in[8];
    const float* dec_bhh = (const float*)d_in[9];
    const float* W1 = (const float*)d_in[10];
    const float* b1 = (const float*)d_in[11];
    const float* W2 = (const float*)d_in[12];
    const float* b2 = (const float*)d_in[13];
    const float* W3 = (const float*)d_in[14];
    const float* b3 = (const float*)d_in[15];
    float* out = (float*)d_out;

    float *enc_xp, *dec_xp, *dec_hs, *m1, *m2, *wte, *wtd;
    cudaGetSymbolAddress((void**)&enc_xp, g_enc_xproj);
    cudaGetSymbolAddress((void**)&dec_xp, g_dec_xproj);
    cudaGetSymbolAddress((void**)&dec_hs, g_dec_hs);
    cudaGetSymbolAddress((void**)&m1,     g_mlp1);
    cudaGetSymbolAddress((void**)&m2,     g_mlp2);
    cudaGetSymbolAddress((void**)&wte,    g_Wt_enc);
    cudaGetSymbolAddress((void**)&wtd,    g_Wt_dec);

    static int smem_set = 0;
    if (!smem_set) {
        cudaFuncSetAttribute(lstm_persistent_kernel,
                             cudaFuncAttributeMaxDynamicSharedMemorySize, LSTM_SMEM);
        smem_set = 1;
    }

    zero_hc_kernel<<<(Bq * Hq + 255) / 256, 256>>>();

    prep_w_kernel<<<4096, 256>>>(enc_Whh, (float4*)wte);
    prep_w_kernel<<<4096, 256>>>(dec_Whh, (float4*)wtd);

    gemm_tf32_kernel<<<dim3(G4 / 128, MTOT / 128), 256>>>(
        input_seq, enc_Wih, enc_bih, enc_bhh, enc_xp, MTOT, G4, 256, 0);
    gemm_tf32_kernel<<<dim3(G4 / 128, MTOT / 128), 256>>>(
        target_seq, dec_Wih, dec_bih, dec_bhh, dec_xp, MTOT, G4, Hq, 0);

    lstm_persistent_kernel<<<NCTA, 256, LSTM_SMEM>>>(enc_xp, dec_xp, dec_hs);

    gemm_tf32_kernel<<<dim3(256 / 128, MTOT / 128), 256>>>(
        dec_hs, W1, b1, nullptr, m1, MTOT, 256, Hq, 1);
    gemm_tf32_kernel<<<dim3(128 / 128, MTOT / 128), 256>>>(
        m1, W2, b2, nullptr, m2, MTOT, 128, 256, 1);
    gemm_tf32_kernel<<<dim3(256 / 128, MTOT / 128), 256>>>(
        m2, W3, b3, nullptr, out, MTOT, 256, 128, 0);
}

// round 9
// speedup vs baseline: 1.1032x; 1.0437x over previous
#include <cuda_runtime.h>
#include <math.h>
#include <stdint.h>

#define Bq   64
#define Tq   512
#define Hq   1024
#define G4   4096
#define MTOT (Bq * Tq)
#define NCTA 128

#define HST     132
#define CHUNK_F (64 * HST)          // 8448 floats per h chunk buffer
#define WB_F    32768               // resident W: 8192 float4
#define LSTM_SMEM ((WB_F + 2 * CHUNK_F) * 4)   // 198656 B
#define REDS 2176                    // per-wk partial slice (64*34, even stride)

// ---------------- device scratch ----------------
__device__ float g_enc_xproj[(size_t)MTOT * G4];
__device__ float g_dec_xproj[(size_t)MTOT * G4];
__device__ float g_dec_hs  [(size_t)MTOT * Hq];
__device__ float g_h       [2 * Bq * Hq];
__device__ float g_mlp1    [(size_t)MTOT * 256];
__device__ float g_mlp2    [(size_t)MTOT * 128];
__device__ float g_Wt_enc  [(size_t)G4 * Hq];   // fragment-packed per CTA
__device__ float g_Wt_dec  [(size_t)G4 * Hq];
__device__ unsigned g_bar;

// ---------------- helpers ----------------
__device__ __forceinline__ float tf32r(float x) {
    uint32_t u; asm("cvt.rna.tf32.f32 %0, %1;" : "=r"(u) : "f"(x));
    return __uint_as_float(u);
}
__device__ __forceinline__ uint32_t fu(float x) { return __float_as_uint(x); }
__device__ __forceinline__ void mma_tf32(float c[4],
    uint32_t a0, uint32_t a1, uint32_t a2, uint32_t a3, uint32_t b0, uint32_t b1) {
    asm volatile(
        "mma.sync.aligned.m16n8k8.row.col.f32.tf32.tf32.f32 "
        "{%0,%1,%2,%3}, {%4,%5,%6,%7}, {%8,%9}, {%0,%1,%2,%3};"
        : "+f"(c[0]), "+f"(c[1]), "+f"(c[2]), "+f"(c[3])
        : "r"(a0), "r"(a1), "r"(a2), "r"(a3), "r"(b0), "r"(b1));
}
__device__ __forceinline__ float sigm(float x) { return 1.f / (1.f + expf(-x)); }
__device__ __forceinline__ void cp16(uint32_t dst, const float* src) {
    asm volatile("cp.async.cg.shared.global [%0], [%1], 16;" :: "r"(dst), "l"(src));
}
__device__ __forceinline__ void cp_commit() {
    asm volatile("cp.async.commit_group;");
}
template<int N> __device__ __forceinline__ void cp_wait() {
    asm volatile("cp.async.wait_group %0;" :: "n"(N));
}

// ---------------- init ----------------
__global__ void zero_hc_kernel() {
    int i = blockIdx.x * blockDim.x + threadIdx.x;
    if (i < Bq * Hq) g_h[i] = 0.f;
    if (i == 0) g_bar = 0u;
}

// ---------------- Whh prep: enc + dec in ONE kernel --------------------------
__global__ __launch_bounds__(256)
void prep_w_kernel(const float* __restrict__ WhhE, const float* __restrict__ WhhD,
                   float4* __restrict__ WtE, float4* __restrict__ WtD) {
    const int half = (blockIdx.x >= 4096);
    const float* Whh = half ? WhhD : WhhE;
    float4* Wt4      = half ? WtD  : WtE;
    int idx  = (blockIdx.x & 4095) * 256 + threadIdx.x;
    int lane = idx & 31;
    int p    = (idx >> 5) & 1;
    int gks  = (idx >> 6) & 127;
    int cta  = idx >> 13;
    int g = lane >> 2, tq = lane & 3;
    int k0 = gks * 8 + tq, k1 = k0 + 4;
    int c0 = p * 16 + g,  c1 = c0 + 8;
    size_t r0 = (size_t)((c0 >> 3) * Hq + cta * 8 + (c0 & 7)) * Hq;
    size_t r1 = (size_t)((c1 >> 3) * Hq + cta * 8 + (c1 & 7)) * Hq;
    float4 v;
    v.x = tf32r(Whh[r0 + k0]); v.y = tf32r(Whh[r0 + k1]);
    v.z = tf32r(Whh[r1 + k0]); v.w = tf32r(Whh[r1 + k1]);
    Wt4[idx] = v;
}

// ---------------- tf32 GEMM (unchanged, proven) -------------------------------
__global__ __launch_bounds__(256)
void gemm_tf32_kernel(const float* __restrict__ A, const float* __restrict__ W,
                      const float* __restrict__ bias1, const float* __restrict__ bias2,
                      float* __restrict__ C, int M, int N, int K, int relu)
{
    __shared__ float As[32][132];
    __shared__ float Bs[32][132];
    const int tid = threadIdx.x;
    const int lane = tid & 31, wid = tid >> 5;
    const int g = lane >> 2, tq = lane & 3;
    const int wm = wid >> 1, wn = wid & 1;
    const int bm = blockIdx.y * 128, bn = blockIdx.x * 128;
    const int kq = tid & 7, lr = tid >> 3;

    float acc[2][8][4] = {};
    float4 pa[4], pb[4];

#pragma unroll
    for (int p = 0; p < 4; p++) {
        pa[p] = *(const float4*)&A[(size_t)(bm + lr + p * 32) * K + kq * 4];
        pb[p] = *(const float4*)&W[(size_t)(bn + lr + p * 32) * K + kq * 4];
    }
#pragma unroll
    for (int p = 0; p < 4; p++) {
        int m = lr + p * 32;
        As[kq*4+0][m] = tf32r(pa[p].x); As[kq*4+1][m] = tf32r(pa[p].y);
        As[kq*4+2][m] = tf32r(pa[p].z); As[kq*4+3][m] = tf32r(pa[p].w);
        Bs[kq*4+0][m] = tf32r(pb[p].x); Bs[kq*4+1][m] = tf32r(pb[p].y);
        Bs[kq*4+2][m] = tf32r(pb[p].z); Bs[kq*4+3][m] = tf32r(pb[p].w);
    }
    __syncthreads();

    const int NK = K / 32;
    for (int kt = 0; kt < NK; kt++) {
        if (kt + 1 < NK) {
            int k0 = (kt + 1) * 32;
#pragma unroll
            for (int p = 0; p < 4; p++) {
                pa[p] = *(const float4*)&A[(size_t)(bm + lr + p * 32) * K + k0 + kq * 4];
                pb[p] = *(const float4*)&W[(size_t)(bn + lr + p * 32) * K + k0 + kq * 4];
            }
        }
#pragma unroll
        for (int ks = 0; ks < 4; ks++) {
            const int kb = ks * 8;
            uint32_t a[2][4], b[8][2];
#pragma unroll
            for (int mf = 0; mf < 2; mf++) {
                int r = wm * 32 + mf * 16 + g;
                a[mf][0] = fu(As[kb + tq][r]);     a[mf][1] = fu(As[kb + tq][r + 8]);
                a[mf][2] = fu(As[kb + tq + 4][r]); a[mf][3] = fu(As[kb + tq + 4][r + 8]);
            }
#pragma unroll
            for (int nf = 0; nf < 8; nf++) {
                int cn = wn * 64 + nf * 8 + g;
                b[nf][0] = fu(Bs[kb + tq][cn]);
                b[nf][1] = fu(Bs[kb + tq + 4][cn]);
            }
#pragma unroll
            for (int mf = 0; mf < 2; mf++)
#pragma unroll
                for (int nf = 0; nf < 8; nf++)
                    mma_tf32(acc[mf][nf], a[mf][0], a[mf][1], a[mf][2], a[mf][3],
                             b[nf][0], b[nf][1]);
        }
        __syncthreads();
        if (kt + 1 < NK) {
#pragma unroll
            for (int p = 0; p < 4; p++) {
                int m = lr + p * 32;
                As[kq*4+0][m] = tf32r(pa[p].x); As[kq*4+1][m] = tf32r(pa[p].y);
                As[kq*4+2][m] = tf32r(pa[p].z); As[kq*4+3][m] = tf32r(pa[p].w);
                Bs[kq*4+0][m] = tf32r(pb[p].x); Bs[kq*4+1][m] = tf32r(pb[p].y);
                Bs[kq*4+2][m] = tf32r(pb[p].z); Bs[kq*4+3][m] = tf32r(pb[p].w);
            }
            __syncthreads();
        }
    }

#pragma unroll
    for (int mf = 0; mf < 2; mf++) {
        int row = bm + wm * 32 + mf * 16 + g;
#pragma unroll
        for (int nf = 0; nf < 8; nf++) {
            int col = bn + wn * 64 + nf * 8 + 2 * tq;
            float b0 = 0.f, b1 = 0.f;
            if (bias1) { b0 = bias1[col]; b1 = bias1[col + 1]; }
            if (bias2) { b0 += bias2[col]; b1 += bias2[col + 1]; }
            float v0 = acc[mf][nf][0] + b0, v1 = acc[mf][nf][1] + b1;
            float v2 = acc[mf][nf][2] + b0, v3 = acc[mf][nf][3] + b1;
            if (relu) { v0 = fmaxf(v0, 0.f); v1 = fmaxf(v1, 0.f);
                        v2 = fmaxf(v2, 0.f); v3 = fmaxf(v3, 0.f); }
            float2 lo = {v0, v1}, hi = {v2, v3};
            *(float2*)&C[(size_t)row * N + col] = lo;
            *(float2*)&C[(size_t)(row + 8) * N + col] = hi;
        }
    }
}

// ---------------- grid barrier -----------------------------------------------
__device__ __forceinline__ void grid_bar(unsigned target) {
    __syncthreads();
    if (threadIdx.x == 0) {
        __threadfence();
        atomicAdd(&g_bar, 1u);
        volatile unsigned* p = &g_bar;
        while (*p < target) { }
        __threadfence();
    }
    __syncthreads();
}

// ---------------- persistent LSTM recurrence: 16 warps, cp.async -------------
__global__ __launch_bounds__(512, 1)
void lstm_persistent_kernel(const float* __restrict__ enc_xp,
                            const float* __restrict__ dec_xp,
                            float* __restrict__ dec_hs)
{
    extern __shared__ float smem[];
    float4* Wb4 = (float4*)smem;            // resident W (128 KB)
    float*  HsA = smem + WB_F;              // 2 h chunk buffers (Red aliases buf0)
    float*  Red = HsA;

    uint32_t smem_u32;
    { uint32_t a; asm("{ .reg .u64 t; cvta.to.shared.u64 t, %1; cvt.u32.u64 %0, t; }"
                      : "=r"(a) : "l"(smem)); smem_u32 = a; }
    const uint32_t hs_u32 = smem_u32 + WB_F * 4;

    const int tid  = threadIdx.x;
    const int lane = tid & 31, wid = tid >> 5;
    const int g = lane >> 2, tq = lane & 3;
    const int wk = wid >> 3;                 // k-half 0/1
    const int wm = (wid >> 1) & 3;           // m-group 0..3
    const int wn = wid & 1;                  // n-group 0/1
    const int r0 = wm * 16 + g;
    const int j0 = blockIdx.x * 8;
    const int ldrow = tid >> 5;              // staging: 16 rows/pass
    const int ldc4  = lane * 4;
    const int pm = tid >> 3;                 // pointwise row 0..63
    const int pj = tid & 7;                  // pointwise col 0..7
    const int pcol = j0 + pj;

    const float4* WtE = (const float4*)g_Wt_enc + (size_t)blockIdx.x * 8192;
    const float4* WtD = (const float4*)g_Wt_dec + (size_t)blockIdx.x * 8192;

    float creg = 0.f;                        // cell state (1 col/thread)

    for (int s = 0; s < 2 * Tq; s++) {
        const int enc = (s < Tq);
        const int t   = enc ? s : (s - Tq);
        const float* __restrict__ xproj = enc ? enc_xp : dec_xp;
        const float* __restrict__ h_in  = g_h + (s & 1) * (Bq * Hq);
        float* __restrict__ h_out       = g_h + ((s + 1) & 1) * (Bq * Hq);

        if (s == 0 || s == Tq) {             // resident W, once per phase
            const float4* src = enc ? WtE : WtD;
#pragma unroll
            for (int j = 0; j < 16; j++) Wb4[j * 512 + tid] = src[j * 512 + tid];
            __syncthreads();
        }

        // stage chunk 0 via cp.async
#pragma unroll
        for (int p = 0; p < 4; p++) {
            int row = p * 16 + ldrow;
            cp16(hs_u32 + (uint32_t)(row * HST + ldc4) * 4,
                 &h_in[row * Hq + ldc4]);
        }
        cp_commit();

        // prefetch xproj gates (1 col per thread)
        float xg0, xg1, xg2, xg3;
        {
            size_t xb = ((size_t)pm * Tq + t) * G4 + pcol;
            xg0 = xproj[xb];
            xg1 = xproj[xb + Hq];
            xg2 = xproj[xb + 2 * Hq];
            xg3 = xproj[xb + 3 * Hq];
        }

        float acc[2][4] = {};

        for (int kt = 0; kt < 8; kt++) {
            if (kt < 7) {                    // stage next chunk
                const int k0 = (kt + 1) * 128;
                const uint32_t dstb = hs_u32 + (uint32_t)(((kt + 1) & 1) * CHUNK_F) * 4;
#pragma unroll
                for (int p = 0; p < 4; p++) {
                    int row = p * 16 + ldrow;
                    cp16(dstb + (uint32_t)(row * HST + ldc4) * 4,
                         &h_in[row * Hq + k0 + ldc4]);
                }
                cp_commit();
                cp_wait<1>();
            } else {
                cp_wait<0>();
            }
            __syncthreads();

            const float* Hs = HsA + (kt & 1) * CHUNK_F;
#pragma unroll
            for (int ks = 0; ks < 8; ks++) {
                const int kl = wk * 8 + ks;          // k8-step in chunk
                const int kb = kl * 8;
                float4 wv = Wb4[(((kt * 16 + kl) * 2) + wn) * 32 + lane];
                uint32_t a0 = fu(Hs[r0 * HST + kb + tq]);
                uint32_t a1 = fu(Hs[(r0 + 8) * HST + kb + tq]);
                uint32_t a2 = fu(Hs[r0 * HST + kb + tq + 4]);
                uint32_t a3 = fu(Hs[(r0 + 8) * HST + kb + tq + 4]);
                mma_tf32(acc[0], a0, a1, a2, a3, fu(wv.x), fu(wv.y));
                mma_tf32(acc[1], a0, a1, a2, a3, fu(wv.z), fu(wv.w));
            }
            __syncthreads();
        }

        // per-wk partials, stride 34 (even -> float2 stores 8B-aligned)
        {
            float* Rw = Red + wk * REDS;
            int cb = wn * 16;
#pragma unroll
            for (int nt = 0; nt < 2; nt++) {
                int col = cb + nt * 8 + 2 * tq;
                float2 lo = {acc[nt][0], acc[nt][1]};
                float2 hi = {acc[nt][2], acc[nt][3]};
                *(float2*)&Rw[r0 * 34 + col]       = lo;
                *(float2*)&Rw[(r0 + 8) * 34 + col] = hi;
            }
        }
        __syncthreads();

        // fused reduce(wk) + pointwise: 1 column per thread
        {
            const float* c0p = &Red[pm * 34 + pj];
            const float* c1p = &Red[REDS + pm * 34 + pj];
            float ig = c0p[0]  + c1p[0]  + xg0;
            float fg = c0p[8]  + c1p[8]  + xg1;
            float gg = c0p[16] + c1p[16] + xg2;
            float og = c0p[24] + c1p[24] + xg3;
            float cn = sigm(fg) * creg + sigm(ig) * tanhf(gg);
            creg = cn;
            float hn = tf32r(sigm(og) * tanhf(cn));   // rounded at production
            h_out[pm * Hq + pcol] = hn;
            if (!enc) dec_hs[((size_t)pm * Tq + t) * Hq + pcol] = hn;
        }

        grid_bar((unsigned)(s + 1) * NCTA);
    }
}

// ---------------- host driver ------------------------------------------------
extern "C" void kernel_launch(void* const* d_in, const int* in_sizes, int n_in,
                              void* d_out, int out_size)
{
    const float* input_seq  = (const float*)d_in[0];
    const float* target_seq = (const float*)d_in[1];
    const float* enc_Wih = (const float*)d_in[2];
    const float* enc_Whh = (const float*)d_in[3];
    const float* enc_bih = (const float*)d_in[4];
    const float* enc_bhh = (const float*)d_in[5];
    const float* dec_Wih = (const float*)d_in[6];
    const float* dec_Whh = (const float*)d_in[7];
    const float* dec_bih = (const float*)d_in[8];
    const float* dec_bhh = (const float*)d_in[9];
    const float* W1 = (const float*)d_in[10];
    const float* b1 = (const float*)d_in[11];
    const float* W2 = (const float*)d_in[12];
    const float* b2 = (const float*)d_in[13];
    const float* W3 = (const float*)d_in[14];
    const float* b3 = (const float*)d_in[15];
    float* out = (float*)d_out;

    float *enc_xp, *dec_xp, *dec_hs, *m1, *m2, *wte, *wtd;
    cudaGetSymbolAddress((void**)&enc_xp, g_enc_xproj);
    cudaGetSymbolAddress((void**)&dec_xp, g_dec_xproj);
    cudaGetSymbolAddress((void**)&dec_hs, g_dec_hs);
    cudaGetSymbolAddress((void**)&m1,     g_mlp1);
    cudaGetSymbolAddress((void**)&m2,     g_mlp2);
    cudaGetSymbolAddress((void**)&wte,    g_Wt_enc);
    cudaGetSymbolAddress((void**)&wtd,    g_Wt_dec);

    static int smem_set = 0;
    if (!smem_set) {
        cudaFuncSetAttribute(lstm_persistent_kernel,
                             cudaFuncAttributeMaxDynamicSharedMemorySize, LSTM_SMEM);
        smem_set = 1;
    }

    zero_hc_kernel<<<(Bq * Hq + 255) / 256, 256>>>();

    prep_w_kernel<<<8192, 256>>>(enc_Whh, dec_Whh, (float4*)wte, (float4*)wtd);

    gemm_tf32_kernel<<<dim3(G4 / 128, MTOT / 128), 256>>>(
        input_seq, enc_Wih, enc_bih, enc_bhh, enc_xp, MTOT, G4, 256, 0);
    gemm_tf32_kernel<<<dim3(G4 / 128, MTOT / 128), 256>>>(
        target_seq, dec_Wih, dec_bih, dec_bhh, dec_xp, MTOT, G4, Hq, 0);

    lstm_persistent_kernel<<<NCTA, 512, LSTM_SMEM>>>(enc_xp, dec_xp, dec_hs);

    gemm_tf32_kernel<<<dim3(256 / 128, MTOT / 128), 256>>>(
        dec_hs, W1, b1, nullptr, m1, MTOT, 256, Hq, 1);
    gemm_tf32_kernel<<<dim3(128 / 128, MTOT / 128), 256>>>(
        m1, W2, b2, nullptr, m2, MTOT, 128, 256, 1);
    gemm_tf32_kernel<<<dim3(256 / 128, MTOT / 128), 256>>>(
        m2, W3, b3, nullptr, out, MTOT, 256, 128, 0);
}

// round 10
// speedup vs baseline: 1.2622x; 1.1441x over previous
#include <cuda_runtime.h>
#include <math.h>
#include <stdint.h>

#define Bq   64
#define Tq   512
#define Hq   1024
#define G4   4096
#define MTOT (Bq * Tq)
#define NCTA 128

#define WB_F    32768               // resident W: 8192 float4 (128 KB)
#define CHUNK_F 8192                // 64x128 floats, contiguous 32 KB
#define LSTM_SMEM ((WB_F + 2 * CHUNK_F) * 4)   // 196608 B
#define REDS 2176                   // per-wk partial slice (64*34)

// ---------------- device scratch ----------------
__device__ float g_enc_xproj[(size_t)MTOT * G4];
__device__ float g_dec_xproj[(size_t)MTOT * G4];
__device__ float g_dec_hs  [(size_t)MTOT * Hq];
__device__ float g_h       [2 * Bq * Hq];       // [2][8 chunks][64][128], swizzled
__device__ float g_mlp1    [(size_t)MTOT * 256];
__device__ float g_mlp2    [(size_t)MTOT * 128];
__device__ float g_Wt_enc  [(size_t)G4 * Hq];   // fragment-packed per CTA
__device__ float g_Wt_dec  [(size_t)G4 * Hq];
__device__ unsigned g_bar;

// ---------------- helpers ----------------
__device__ __forceinline__ float tf32r(float x) {
    uint32_t u; asm("cvt.rna.tf32.f32 %0, %1;" : "=r"(u) : "f"(x));
    return __uint_as_float(u);
}
__device__ __forceinline__ uint32_t fu(float x) { return __float_as_uint(x); }
__device__ __forceinline__ void mma_tf32(float c[4],
    uint32_t a0, uint32_t a1, uint32_t a2, uint32_t a3, uint32_t b0, uint32_t b1) {
    asm volatile(
        "mma.sync.aligned.m16n8k8.row.col.f32.tf32.tf32.f32 "
        "{%0,%1,%2,%3}, {%4,%5,%6,%7}, {%8,%9}, {%0,%1,%2,%3};"
        : "+f"(c[0]), "+f"(c[1]), "+f"(c[2]), "+f"(c[3])
        : "r"(a0), "r"(a1), "r"(a2), "r"(a3), "r"(b0), "r"(b1));
}
__device__ __forceinline__ float sigm(float x) { return 1.f / (1.f + expf(-x)); }

__device__ __forceinline__ uint32_t smem_addr(const void* p) {
    uint32_t a;
    asm("{ .reg .u64 t; cvta.to.shared.u64 t, %1; cvt.u32.u64 %0, t; }"
        : "=r"(a) : "l"(p));
    return a;
}
__device__ __forceinline__ void mbar_init(uint32_t mbar, uint32_t cnt) {
    asm volatile("mbarrier.init.shared.b64 [%0], %1;" :: "r"(mbar), "r"(cnt) : "memory");
}
__device__ __forceinline__ void mbar_expect_tx(uint32_t mbar, uint32_t bytes) {
    asm volatile("mbarrier.arrive.expect_tx.shared.b64 _, [%0], %1;"
                 :: "r"(mbar), "r"(bytes) : "memory");
}
__device__ __forceinline__ void mbar_wait(uint32_t mbar, uint32_t phase) {
    asm volatile(
        "{\n\t.reg .pred P;\n\t"
        "W%=:\n\t"
        "mbarrier.try_wait.parity.acquire.cta.shared::cta.b64 P, [%0], %1, 0x989680;\n\t"
        "@P bra D%=;\n\t"
        "bra W%=;\n\t"
        "D%=:\n\t}"
        :: "r"(mbar), "r"(phase) : "memory");
}
__device__ __forceinline__ void fence_async() {
    asm volatile("fence.proxy.async.shared::cta;" ::: "memory");
}
__device__ __forceinline__ void bulk_g2s(uint32_t dst, const float* src,
                                         uint32_t bytes, uint32_t mbar) {
    asm volatile(
        "cp.async.bulk.shared::cta.global.mbarrier::complete_tx::bytes [%0], [%1], %2, [%3];"
        :: "r"(dst), "l"(src), "r"(bytes), "r"(mbar) : "memory");
}

// ---------------- init ----------------
__global__ void zero_hc_kernel() {
    int i = blockIdx.x * blockDim.x + threadIdx.x;
    if (i < Bq * Hq) g_h[i] = 0.f;
    if (i == 0) g_bar = 0u;
}

// ---------------- Whh prep: enc + dec in ONE kernel --------------------------
__global__ __launch_bounds__(256)
void prep_w_kernel(const float* __restrict__ WhhE, const float* __restrict__ WhhD,
                   float4* __restrict__ WtE, float4* __restrict__ WtD) {
    const int half = (blockIdx.x >= 4096);
    const float* Whh = half ? WhhD : WhhE;
    float4* Wt4      = half ? WtD  : WtE;
    int idx  = (blockIdx.x & 4095) * 256 + threadIdx.x;
    int lane = idx & 31;
    int p    = (idx >> 5) & 1;
    int gks  = (idx >> 6) & 127;
    int cta  = idx >> 13;
    int g = lane >> 2, tq = lane & 3;
    int k0 = gks * 8 + tq, k1 = k0 + 4;
    int c0 = p * 16 + g,  c1 = c0 + 8;
    size_t r0 = (size_t)((c0 >> 3) * Hq + cta * 8 + (c0 & 7)) * Hq;
    size_t r1 = (size_t)((c1 >> 3) * Hq + cta * 8 + (c1 & 7)) * Hq;
    float4 v;
    v.x = tf32r(Whh[r0 + k0]); v.y = tf32r(Whh[r0 + k1]);
    v.z = tf32r(Whh[r1 + k0]); v.w = tf32r(Whh[r1 + k1]);
    Wt4[idx] = v;
}

// ---------------- tf32 GEMM (unchanged, proven) -------------------------------
__global__ __launch_bounds__(256)
void gemm_tf32_kernel(const float* __restrict__ A, const float* __restrict__ W,
                      const float* __restrict__ bias1, const float* __restrict__ bias2,
                      float* __restrict__ C, int M, int N, int K, int relu)
{
    __shared__ float As[32][132];
    __shared__ float Bs[32][132];
    const int tid = threadIdx.x;
    const int lane = tid & 31, wid = tid >> 5;
    const int g = lane >> 2, tq = lane & 3;
    const int wm = wid >> 1, wn = wid & 1;
    const int bm = blockIdx.y * 128, bn = blockIdx.x * 128;
    const int kq = tid & 7, lr = tid >> 3;

    float acc[2][8][4] = {};
    float4 pa[4], pb[4];

#pragma unroll
    for (int p = 0; p < 4; p++) {
        pa[p] = *(const float4*)&A[(size_t)(bm + lr + p * 32) * K + kq * 4];
        pb[p] = *(const float4*)&W[(size_t)(bn + lr + p * 32) * K + kq * 4];
    }
#pragma unroll
    for (int p = 0; p < 4; p++) {
        int m = lr + p * 32;
        As[kq*4+0][m] = tf32r(pa[p].x); As[kq*4+1][m] = tf32r(pa[p].y);
        As[kq*4+2][m] = tf32r(pa[p].z); As[kq*4+3][m] = tf32r(pa[p].w);
        Bs[kq*4+0][m] = tf32r(pb[p].x); Bs[kq*4+1][m] = tf32r(pb[p].y);
        Bs[kq*4+2][m] = tf32r(pb[p].z); Bs[kq*4+3][m] = tf32r(pb[p].w);
    }
    __syncthreads();

    const int NK = K / 32;
    for (int kt = 0; kt < NK; kt++) {
        if (kt + 1 < NK) {
            int k0 = (kt + 1) * 32;
#pragma unroll
            for (int p = 0; p < 4; p++) {
                pa[p] = *(const float4*)&A[(size_t)(bm + lr + p * 32) * K + k0 + kq * 4];
                pb[p] = *(const float4*)&W[(size_t)(bn + lr + p * 32) * K + k0 + kq * 4];
            }
        }
#pragma unroll
        for (int ks = 0; ks < 4; ks++) {
            const int kb = ks * 8;
            uint32_t a[2][4], b[8][2];
#pragma unroll
            for (int mf = 0; mf < 2; mf++) {
                int r = wm * 32 + mf * 16 + g;
                a[mf][0] = fu(As[kb + tq][r]);     a[mf][1] = fu(As[kb + tq][r + 8]);
                a[mf][2] = fu(As[kb + tq + 4][r]); a[mf][3] = fu(As[kb + tq + 4][r + 8]);
            }
#pragma unroll
            for (int nf = 0; nf < 8; nf++) {
                int cn = wn * 64 + nf * 8 + g;
                b[nf][0] = fu(Bs[kb + tq][cn]);
                b[nf][1] = fu(Bs[kb + tq + 4][cn]);
            }
#pragma unroll
            for (int mf = 0; mf < 2; mf++)
#pragma unroll
                for (int nf = 0; nf < 8; nf++)
                    mma_tf32(acc[mf][nf], a[mf][0], a[mf][1], a[mf][2], a[mf][3],
                             b[nf][0], b[nf][1]);
        }
        __syncthreads();
        if (kt + 1 < NK) {
#pragma unroll
            for (int p = 0; p < 4; p++) {
                int m = lr + p * 32;
                As[kq*4+0][m] = tf32r(pa[p].x); As[kq*4+1][m] = tf32r(pa[p].y);
                As[kq*4+2][m] = tf32r(pa[p].z); As[kq*4+3][m] = tf32r(pa[p].w);
                Bs[kq*4+0][m] = tf32r(pb[p].x); Bs[kq*4+1][m] = tf32r(pb[p].y);
                Bs[kq*4+2][m] = tf32r(pb[p].z); Bs[kq*4+3][m] = tf32r(pb[p].w);
            }
            __syncthreads();
        }
    }

#pragma unroll
    for (int mf = 0; mf < 2; mf++) {
        int row = bm + wm * 32 + mf * 16 + g;
#pragma unroll
        for (int nf = 0; nf < 8; nf++) {
            int col = bn + wn * 64 + nf * 8 + 2 * tq;
            float b0 = 0.f, b1 = 0.f;
            if (bias1) { b0 = bias1[col]; b1 = bias1[col + 1]; }
            if (bias2) { b0 += bias2[col]; b1 += bias2[col + 1]; }
            float v0 = acc[mf][nf][0] + b0, v1 = acc[mf][nf][1] + b1;
            float v2 = acc[mf][nf][2] + b0, v3 = acc[mf][nf][3] + b1;
            if (relu) { v0 = fmaxf(v0, 0.f); v1 = fmaxf(v1, 0.f);
                        v2 = fmaxf(v2, 0.f); v3 = fmaxf(v3, 0.f); }
            float2 lo = {v0, v1}, hi = {v2, v3};
            *(float2*)&C[(size_t)row * N + col] = lo;
            *(float2*)&C[(size_t)(row + 8) * N + col] = hi;
        }
    }
}

// ---------------- grid barrier -----------------------------------------------
__device__ __forceinline__ void grid_bar(unsigned target) {
    __syncthreads();
    if (threadIdx.x == 0) {
        __threadfence();
        atomicAdd(&g_bar, 1u);
        volatile unsigned* p = &g_bar;
        while (*p < target) { }
        __threadfence();
    }
    __syncthreads();
}

// ---------------- persistent LSTM recurrence: bulk-copy staging ---------------
// h layout: [2][8 chunks][64 batch][128 k], element (r,c) of a chunk stored at
// [r*128 + (c ^ ((r&7)<<2))]  -> conflict-free un-padded fragment reads.
__global__ __launch_bounds__(512, 1)
void lstm_persistent_kernel(const float* __restrict__ enc_xp,
                            const float* __restrict__ dec_xp,
                            float* __restrict__ dec_hs)
{
    extern __shared__ float smem[];
    float4* Wb4 = (float4*)smem;            // resident W (128 KB)
    float*  HsA = smem + WB_F;              // buf0 32KB, buf1 32KB
    float*  Red = HsA;                      // partials alias buf0 (17408 B)
    __shared__ __align__(8) unsigned long long mbars[2];

    const uint32_t buf_u32_0 = smem_addr(smem) + WB_F * 4;
    const uint32_t mbar0 = smem_addr(mbars);
    const uint32_t mbar1 = mbar0 + 8;

    const int tid  = threadIdx.x;
    const int lane = tid & 31, wid = tid >> 5;
    const int g = lane >> 2, tq = lane & 3;
    const int wk = wid >> 3;                 // k-half 0/1
    const int wm = (wid >> 1) & 3;           // m-group 0..3
    const int wn = wid & 1;                  // n-group 0/1
    const int r0 = wm * 16 + g;
    const int gx = g << 2;                   // swizzle term ((r&7)<<2), r&7 == g
    const int j0 = blockIdx.x * 8;
    const int pm = tid >> 3;                 // pointwise row 0..63
    const int pj = tid & 7;                  // pointwise col 0..7
    const int pcol = j0 + pj;
    const int pchunk = pcol >> 7;
    const int psw = (pcol & 127) ^ ((pm & 7) << 2);
    const int pdst = pchunk * CHUNK_F + pm * 128 + psw;

    const float4* WtE = (const float4*)g_Wt_enc + (size_t)blockIdx.x * 8192;
    const float4* WtD = (const float4*)g_Wt_dec + (size_t)blockIdx.x * 8192;

    if (tid == 0) { mbar_init(mbar0, 1); mbar_init(mbar1, 1); }
    __syncthreads();
    int ph0 = 0, ph1 = 0;

    float creg = 0.f;

    for (int s = 0; s < 2 * Tq; s++) {
        const int enc = (s < Tq);
        const int t   = enc ? s : (s - Tq);
        const float* __restrict__ xproj = enc ? enc_xp : dec_xp;
        const float* __restrict__ h_in  = g_h + (s & 1) * (Bq * Hq);
        float* __restrict__ h_out       = g_h + ((s + 1) & 1) * (Bq * Hq);

        if (s == 0 || s == Tq) {             // resident W, once per phase
            const float4* src = enc ? WtE : WtD;
#pragma unroll
            for (int j = 0; j < 16; j++) Wb4[j * 512 + tid] = src[j * 512 + tid];
            __syncthreads();
        }

        // prologue: launch bulk copies for chunks 0 and 1 (2-deep pipeline)
        if (tid == 0) {
            fence_async();
            mbar_expect_tx(mbar0, CHUNK_F * 4);
            bulk_g2s(buf_u32_0, h_in, CHUNK_F * 4, mbar0);
            mbar_expect_tx(mbar1, CHUNK_F * 4);
            bulk_g2s(buf_u32_0 + CHUNK_F * 4, h_in + CHUNK_F, CHUNK_F * 4, mbar1);
        }

        // prefetch xproj gates (overlaps with bulk copies)
        float xg0, xg1, xg2, xg3;
        {
            size_t xb = ((size_t)pm * Tq + t) * G4 + pcol;
            xg0 = xproj[xb];
            xg1 = xproj[xb + Hq];
            xg2 = xproj[xb + 2 * Hq];
            xg3 = xproj[xb + 3 * Hq];
        }

        float acc[2][4] = {};

        for (int kt = 0; kt < 8; kt++) {
            if (kt & 1) { mbar_wait(mbar1, ph1); ph1 ^= 1; }
            else        { mbar_wait(mbar0, ph0); ph0 ^= 1; }

            const float* Hs = HsA + (kt & 1) * CHUNK_F;
#pragma unroll
            for (int ks = 0; ks < 8; ks++) {
                const int kl = wk * 8 + ks;          // k8-step in chunk
                const int kb = kl * 8;
                float4 wv = Wb4[(((kt * 16 + kl) * 2) + wn) * 32 + lane];
                const int c0 = (kb + tq) ^ gx;
                const int c1 = (kb + tq + 4) ^ gx;
                uint32_t a0 = fu(Hs[r0 * 128 + c0]);
                uint32_t a1 = fu(Hs[(r0 + 8) * 128 + c0]);
                uint32_t a2 = fu(Hs[r0 * 128 + c1]);
                uint32_t a3 = fu(Hs[(r0 + 8) * 128 + c1]);
                mma_tf32(acc[0], a0, a1, a2, a3, fu(wv.x), fu(wv.y));
                mma_tf32(acc[1], a0, a1, a2, a3, fu(wv.z), fu(wv.w));
            }
            __syncthreads();                  // buffer kt&1 free

            if (kt < 6 && tid == 0) {         // stage chunk kt+2 into freed buffer
                const int b = kt & 1;
                fence_async();
                if (b) { mbar_expect_tx(mbar1, CHUNK_F * 4);
                         bulk_g2s(buf_u32_0 + CHUNK_F * 4,
                                  h_in + (kt + 2) * CHUNK_F, CHUNK_F * 4, mbar1); }
                else   { mbar_expect_tx(mbar0, CHUNK_F * 4);
                         bulk_g2s(buf_u32_0,
                                  h_in + (kt + 2) * CHUNK_F, CHUNK_F * 4, mbar0); }
            }
        }

        // per-wk partials, stride 34 (aliases buf0 — free after kt=7)
        {
            float* Rw = Red + wk * REDS;
            int cb = wn * 16;
#pragma unroll
            for (int nt = 0; nt < 2; nt++) {
                int col = cb + nt * 8 + 2 * tq;
                float2 lo = {acc[nt][0], acc[nt][1]};
                float2 hi = {acc[nt][2], acc[nt][3]};
                *(float2*)&Rw[r0 * 34 + col]       = lo;
                *(float2*)&Rw[(r0 + 8) * 34 + col] = hi;
            }
        }
        __syncthreads();

        // fused reduce(wk) + pointwise: 1 column per thread
        {
            const float* c0p = &Red[pm * 34 + pj];
            const float* c1p = &Red[REDS + pm * 34 + pj];
            float ig = c0p[0]  + c1p[0]  + xg0;
            float fg = c0p[8]  + c1p[8]  + xg1;
            float gg = c0p[16] + c1p[16] + xg2;
            float og = c0p[24] + c1p[24] + xg3;
            float cn = sigm(fg) * creg + sigm(ig) * tanhf(gg);
            creg = cn;
            float hn = tf32r(sigm(og) * tanhf(cn));
            h_out[pdst] = hn;                        // chunk-swizzled layout
            if (!enc) dec_hs[((size_t)pm * Tq + t) * Hq + pcol] = hn;
        }

        grid_bar((unsigned)(s + 1) * NCTA);
    }
}

// ---------------- host driver ------------------------------------------------
extern "C" void kernel_launch(void* const* d_in, const int* in_sizes, int n_in,
                              void* d_out, int out_size)
{
    const float* input_seq  = (const float*)d_in[0];
    const float* target_seq = (const float*)d_in[1];
    const float* enc_Wih = (const float*)d_in[2];
    const float* enc_Whh = (const float*)d_in[3];
    const float* enc_bih = (const float*)d_in[4];
    const float* enc_bhh = (const float*)d_in[5];
    const float* dec_Wih = (const float*)d_in[6];
    const float* dec_Whh = (const float*)d_in[7];
    const float* dec_bih = (const float*)d_in[8];
    const float* dec_bhh = (const float*)d_in[9];
    const float* W1 = (const float*)d_in[10];
    const float* b1 = (const float*)d_in[11];
    const float* W2 = (const float*)d_in[12];
    const float* b2 = (const float*)d_in[13];
    const float* W3 = (const float*)d_in[14];
    const float* b3 = (const float*)d_in[15];
    float* out = (float*)d_out;

    float *enc_xp, *dec_xp, *dec_hs, *m1, *m2, *wte, *wtd;
    cudaGetSymbolAddress((void**)&enc_xp, g_enc_xproj);
    cudaGetSymbolAddress((void**)&dec_xp, g_dec_xproj);
    cudaGetSymbolAddress((void**)&dec_hs, g_dec_hs);
    cudaGetSymbolAddress((void**)&m1,     g_mlp1);
    cudaGetSymbolAddress((void**)&m2,     g_mlp2);
    cudaGetSymbolAddress((void**)&wte,    g_Wt_enc);
    cudaGetSymbolAddress((void**)&wtd,    g_Wt_dec);

    static int smem_set = 0;
    if (!smem_set) {
        cudaFuncSetAttribute(lstm_persistent_kernel,
                             cudaFuncAttributeMaxDynamicSharedMemorySize, LSTM_SMEM);
        smem_set = 1;
    }

    zero_hc_kernel<<<(Bq * Hq + 255) / 256, 256>>>();

    prep_w_kernel<<<8192, 256>>>(enc_Whh, dec_Whh, (float4*)wte, (float4*)wtd);

    gemm_tf32_kernel<<<dim3(G4 / 128, MTOT / 128), 256>>>(
        input_seq, enc_Wih, enc_bih, enc_bhh, enc_xp, MTOT, G4, 256, 0);
    gemm_tf32_kernel<<<dim3(G4 / 128, MTOT / 128), 256>>>(
        target_seq, dec_Wih, dec_bih, dec_bhh, dec_xp, MTOT, G4, Hq, 0);

    lstm_persistent_kernel<<<NCTA, 512, LSTM_SMEM>>>(enc_xp, dec_xp, dec_hs);

    gemm_tf32_kernel<<<dim3(256 / 128, MTOT / 128), 256>>>(
        dec_hs, W1, b1, nullptr, m1, MTOT, 256, Hq, 1);
    gemm_tf32_kernel<<<dim3(128 / 128, MTOT / 128), 256>>>(
        m1, W2, b2, nullptr, m2, MTOT, 128, 256, 1);
    gemm_tf32_kernel<<<dim3(256 / 128, MTOT / 128), 256>>>(
        m2, W3, b3, nullptr, out, MTOT, 256, 128, 0);
}